// round 1
// baseline (speedup 1.0000x reference)
#include <cuda_runtime.h>

#define SDIM 4096
#define DDIM 64
#define TM 128
#define TN 128
#define JSPLIT 4
#define ROWB (SDIM / TM)                 /* 32 */
#define TILES_PER_CTA (SDIM / (TN * JSPLIT)) /* 8 */
#define NCTA (ROWB * JSPLIT)             /* 128 */

#define QT_STRIDE 132
#define KT_STRIDE 132
#define TS_STRIDE 132
#define SM_QT 0
#define SM_KT (64 * 132)
#define SM_VS (2 * 64 * 132)
#define SM_TS (2 * 64 * 132 + 128 * 64)
#define SMEM_FLOATS (SM_TS + 128 * 132)
#define SMEM_BYTES (SMEM_FLOATS * 4)

// Scratch (no cudaMalloc allowed): per-jsplit partial outputs + per-CTA r-sums.
__device__ float g_outpart[JSPLIT][SDIM][DDIM];
__device__ float g_rpart[NCTA];

// Packed f32x2 helpers (Blackwell sm_100+). Per-lane IEEE rn — bitwise identical
// to scalar fmaf, so the floor() stays consistent with a scalar reference.
#define FMA2(acc, a, b) \
    asm("fma.rn.f32x2 %0, %1, %2, %0;" : "+l"(acc) : "l"(a), "l"(b))
#define PACKDUP(d, f) \
    asm("mov.b64 %0, {%1, %1};" : "=l"(d) : "r"(__float_as_uint(f)))
#define UNPACK2(lo, hi, v) do {                                   \
    unsigned int _ulo, _uhi;                                      \
    asm("mov.b64 {%0, %1}, %2;" : "=r"(_ulo), "=r"(_uhi) : "l"(v)); \
    lo = __uint_as_float(_ulo); hi = __uint_as_float(_uhi);       \
} while (0)

__global__ void __launch_bounds__(256, 1) fused_attn_main(
    const float* __restrict__ Q, const float* __restrict__ K,
    const float* __restrict__ V, const float* __restrict__ U,
    const float* __restrict__ RR)
{
    extern __shared__ float sm[];
    float* Qt = sm + SM_QT;   // [64][132]  Qt[k][i]
    float* Kt = sm + SM_KT;   // [64][132]  Kt[k][j]
    float* Vs = sm + SM_VS;   // [128][64]  Vs[j][d]
    float* Ts = sm + SM_TS;   // [128][132] Ts[i][j]  (t*r tile)

    const int tid = threadIdx.x;
    const int tx = tid & 15;        // 16: j / d dimension
    const int ty = tid >> 4;        // 16: i dimension
    const int i0 = blockIdx.y * TM;
    const int jbase = blockIdx.x * (SDIM / JSPLIT);

    // ---- load Q tile transposed: Qt[k][i] ----
#pragma unroll
    for (int it = 0; it < 8; ++it) {
        int r = it * 16 + ty;
        float4 q = *(const float4*)(Q + (size_t)(i0 + r) * DDIM + tx * 4);
        Qt[(tx * 4 + 0) * QT_STRIDE + r] = q.x;
        Qt[(tx * 4 + 1) * QT_STRIDE + r] = q.y;
        Qt[(tx * 4 + 2) * QT_STRIDE + r] = q.z;
        Qt[(tx * 4 + 3) * QT_STRIDE + r] = q.w;
    }

    float rr[8];
#pragma unroll
    for (int ii = 0; ii < 8; ++ii) rr[ii] = RR[i0 + ty * 8 + ii];

    // out accumulators: 8 rows x 4 d-cols as packed pairs
    unsigned long long o2[8][2];
#pragma unroll
    for (int ii = 0; ii < 8; ++ii) { o2[ii][0] = 0ull; o2[ii][1] = 0ull; }
    float rsum = 0.0f;

    const float CF = 8.0f / 0.9f;  // sqrt(64) * 1/(1-p); x8 is exact so rounding
                                   // matches the reference's qk*8 then /0.9 order.

    for (int jt = 0; jt < TILES_PER_CTA; ++jt) {
        const int j0 = jbase + jt * TN;
        __syncthreads();  // previous tile's GEMM2 done before refill

        // ---- fill Kt[k][j] (transposed) ----
#pragma unroll
        for (int it = 0; it < 8; ++it) {
            int r = it * 16 + ty;
            float4 kv = *(const float4*)(K + (size_t)(j0 + r) * DDIM + tx * 4);
            Kt[(tx * 4 + 0) * KT_STRIDE + r] = kv.x;
            Kt[(tx * 4 + 1) * KT_STRIDE + r] = kv.y;
            Kt[(tx * 4 + 2) * KT_STRIDE + r] = kv.z;
            Kt[(tx * 4 + 3) * KT_STRIDE + r] = kv.w;
        }
        // ---- fill Vs[j][d] (direct copy) ----
#pragma unroll
        for (int it = 0; it < 8; ++it) {
            int v = it * 256 + tid;
            int row = v >> 4, c4 = (v & 15) << 2;
            *(float4*)(Vs + row * 64 + c4) =
                *(const float4*)(V + (size_t)(j0 + row) * DDIM + c4);
        }
        __syncthreads();

        // ---- GEMM1: S = Q @ K^T  (8x8 micro, f32x2 packed) ----
        // thread's j cols: {tx*4+0..3} and {64+tx*4+0..3}
        unsigned long long s2[8][4];
#pragma unroll
        for (int ii = 0; ii < 8; ++ii)
#pragma unroll
            for (int jp = 0; jp < 4; ++jp) s2[ii][jp] = 0ull;

#pragma unroll 4
        for (int k = 0; k < 64; ++k) {
            const float* qrow = Qt + k * QT_STRIDE + ty * 8;
            float4 a0 = *(const float4*)(qrow);
            float4 a1 = *(const float4*)(qrow + 4);
            const float* krow = Kt + k * KT_STRIDE + tx * 4;
            ulonglong2 b0 = *(const ulonglong2*)(krow);       // pairs (j0,j1),(j2,j3)
            ulonglong2 b1 = *(const ulonglong2*)(krow + 64);  // second chunk
            unsigned long long a2[8];
            PACKDUP(a2[0], a0.x); PACKDUP(a2[1], a0.y);
            PACKDUP(a2[2], a0.z); PACKDUP(a2[3], a0.w);
            PACKDUP(a2[4], a1.x); PACKDUP(a2[5], a1.y);
            PACKDUP(a2[6], a1.z); PACKDUP(a2[7], a1.w);
#pragma unroll
            for (int ii = 0; ii < 8; ++ii) {
                FMA2(s2[ii][0], a2[ii], b0.x);
                FMA2(s2[ii][1], a2[ii], b0.y);
                FMA2(s2[ii][2], a2[ii], b1.x);
                FMA2(s2[ii][3], a2[ii], b1.y);
            }
        }

        // ---- elementwise: dropout, floor mask, accumulate R, write t*r tile ----
#pragma unroll
        for (int ii = 0; ii < 8; ++ii) {
            const int gi = i0 + ty * 8 + ii;
            const float* urow = U + (size_t)gi * SDIM + j0;
            float4 u0 = *(const float4*)(urow + tx * 4);
            float4 u1 = *(const float4*)(urow + 64 + tx * 4);
            float sv[8];
            UNPACK2(sv[0], sv[1], s2[ii][0]);
            UNPACK2(sv[2], sv[3], s2[ii][1]);
            UNPACK2(sv[4], sv[5], s2[ii][2]);
            UNPACK2(sv[6], sv[7], s2[ii][3]);
            const float uu[8] = {u0.x, u0.y, u0.z, u0.w, u1.x, u1.y, u1.z, u1.w};
            float tv[8];
            const float rrv = rr[ii];
#pragma unroll
            for (int e = 0; e < 8; ++e) {
                float t = (uu[e] >= 0.1f) ? sv[e] * CF : 0.0f;
                float rv = floorf(t * rrv);
                rsum += rv;
                tv[e] = t * rv;
            }
            float* trow = Ts + (ty * 8 + ii) * TS_STRIDE + tx * 4;
            *(float4*)(trow)      = make_float4(tv[0], tv[1], tv[2], tv[3]);
            *(float4*)(trow + 64) = make_float4(tv[4], tv[5], tv[6], tv[7]);
        }
        __syncthreads();

        // ---- GEMM2: out_acc += T @ V  (a-reads are 16-thread broadcasts) ----
#pragma unroll 4
        for (int jj = 0; jj < 128; ++jj) {
            ulonglong2 bv = *(const ulonglong2*)(Vs + jj * 64 + tx * 4);
            const float* tcol = Ts + (ty * 8) * TS_STRIDE + jj;
#pragma unroll
            for (int ii = 0; ii < 8; ++ii) {
                float av = tcol[ii * TS_STRIDE];
                unsigned long long a2;
                PACKDUP(a2, av);
                FMA2(o2[ii][0], a2, bv.x);
                FMA2(o2[ii][1], a2, bv.y);
            }
        }
    }

    // ---- epilogue: write partial output (no atomics -> deterministic) ----
#pragma unroll
    for (int ii = 0; ii < 8; ++ii) {
        float x0, x1, x2, x3;
        UNPACK2(x0, x1, o2[ii][0]);
        UNPACK2(x2, x3, o2[ii][1]);
        const int gi = i0 + ty * 8 + ii;
        *(float4*)(&g_outpart[blockIdx.x][gi][tx * 4]) =
            make_float4(x0, x1, x2, x3);
    }

    // ---- deterministic block reduction of rsum ----
#pragma unroll
    for (int off = 16; off; off >>= 1)
        rsum += __shfl_xor_sync(0xffffffffu, rsum, off);
    float* red = sm;  // reuse Qt region (all warps are past the GEMM2 barrier)
    if ((tid & 31) == 0) red[tid >> 5] = rsum;
    __syncthreads();
    if (tid == 0) {
        float tot = 0.0f;
        for (int w = 0; w < 8; ++w) tot += red[w];
        g_rpart[blockIdx.y * JSPLIT + blockIdx.x] = tot;
    }
}

// Reduce R deterministically (same tree in every block) and finalize output.
__global__ void __launch_bounds__(256) finalize_kernel(float* __restrict__ out)
{
    __shared__ float red[128];
    const int tid = threadIdx.x;
    if (tid < 128) red[tid] = g_rpart[tid];
    __syncthreads();
#pragma unroll
    for (int s = 64; s > 0; s >>= 1) {
        if (tid < s) red[tid] += red[tid + s];
        __syncthreads();
    }
    const float R = red[0];

    const int idx = blockIdx.x * 256 + tid;  // one float4 per thread
    const float* base = &g_outpart[0][0][0];
    const size_t part = (size_t)SDIM * DDIM;
    float4 a = *(const float4*)(base + (size_t)idx * 4);
    float4 b = *(const float4*)(base + part + (size_t)idx * 4);
    float4 c = *(const float4*)(base + 2 * part + (size_t)idx * 4);
    float4 d = *(const float4*)(base + 3 * part + (size_t)idx * 4);
    float4 o;
    o.x = (((a.x + b.x) + c.x) + d.x) / R;
    o.y = (((a.y + b.y) + c.y) + d.y) / R;
    o.z = (((a.z + b.z) + c.z) + d.z) / R;
    o.w = (((a.w + b.w) + c.w) + d.w) / R;
    *(float4*)(out + (size_t)idx * 4) = o;
}

extern "C" void kernel_launch(void* const* d_in, const int* in_sizes, int n_in,
                              void* d_out, int out_size)
{
    const float* Q  = (const float*)d_in[0];
    const float* K  = (const float*)d_in[1];
    const float* V  = (const float*)d_in[2];
    const float* U  = (const float*)d_in[3];
    const float* RR = (const float*)d_in[4];
    float* out = (float*)d_out;

    cudaFuncSetAttribute(fused_attn_main,
                         cudaFuncAttributeMaxDynamicSharedMemorySize, SMEM_BYTES);

    dim3 grid(JSPLIT, ROWB);
    fused_attn_main<<<grid, 256, SMEM_BYTES>>>(Q, K, V, U, RR);
    finalize_kernel<<<(SDIM * DDIM) / (4 * 256), 256>>>(out);
}

// round 2
// speedup vs baseline: 1.0311x; 1.0311x over previous
#include <cuda_runtime.h>

#define SDIM 4096
#define DDIM 64
#define TM 128
#define TN 128
#define JSPLIT 4
#define ROWB (SDIM / TM)                     /* 32 */
#define TILES_PER_CTA (SDIM / (TN * JSPLIT)) /* 8 */
#define NCTA (ROWB * JSPLIT)                 /* 128 */
#define NTHREADS 512

#define QT_STRIDE 132
#define KT_STRIDE 132
#define TST_STRIDE 132
#define SM_QT 0
#define SM_KT (64 * 132)
#define SM_VS (2 * 64 * 132)
#define SM_TS (2 * 64 * 132 + 128 * 64)
#define SMEM_FLOATS (SM_TS + 128 * 132)
#define SMEM_BYTES (SMEM_FLOATS * 4)

// Scratch (no cudaMalloc allowed): per-jsplit partial outputs + per-CTA r-sums.
__device__ float g_outpart[JSPLIT][SDIM][DDIM];
__device__ float g_rpart[NCTA];

// Packed f32x2 helpers (Blackwell). Per-lane IEEE rn — bitwise identical to
// scalar fmaf, so floor() behavior matches a scalar reference exactly.
#define FMA2(acc, a, b) \
    asm("fma.rn.f32x2 %0, %1, %2, %0;" : "+l"(acc) : "l"(a), "l"(b))
#define PACKDUP(d, f) \
    asm("mov.b64 %0, {%1, %1};" : "=l"(d) : "r"(__float_as_uint(f)))
#define UNPACK2(lo, hi, v) do {                                     \
    unsigned int _ulo, _uhi;                                        \
    asm("mov.b64 {%0, %1}, %2;" : "=r"(_ulo), "=r"(_uhi) : "l"(v)); \
    lo = __uint_as_float(_ulo); hi = __uint_as_float(_uhi);         \
} while (0)

__global__ void __launch_bounds__(NTHREADS, 1) fused_attn_main(
    const float* __restrict__ Q, const float* __restrict__ K,
    const float* __restrict__ V, const float* __restrict__ U,
    const float* __restrict__ RR)
{
    extern __shared__ float sm[];
    float* Qt = sm + SM_QT;   // [64][132]  Qt[k][i]  (i-group XOR-swizzled by k)
    float* Kt = sm + SM_KT;   // [64][132]  Kt[k][j]  (j-group XOR-swizzled by k)
    float* Vs = sm + SM_VS;   // [128][64]  Vs[j][d]
    float* Ts = sm + SM_TS;   // [128][132] Ts[j][i]  (i-group XOR-swizzled by j)

    const int tid = threadIdx.x;
    const int tx = tid & 15;        // 16: j-group / d-group
    const int ty = tid >> 4;        // 32: i-group (4 rows each)
    const int i0 = blockIdx.y * TM;
    const int jbase = blockIdx.x * (SDIM / JSPLIT);
    const int gsw = tx & 7;         // swizzle key for this thread's k/j rows

    // ---- load Q tile transposed + swizzled: Qt[k][swz(i,k)] ----
#pragma unroll
    for (int it = 0; it < 4; ++it) {
        int r = it * 32 + ty;                       // i row
        float4 q = *(const float4*)(Q + (size_t)(i0 + r) * DDIM + tx * 4);
        int base = 4 * ((r >> 2) ^ gsw) + (r & 3);  // g(k)=(k>>2)&7 = tx&7
        Qt[(tx * 4 + 0) * QT_STRIDE + base] = q.x;
        Qt[(tx * 4 + 1) * QT_STRIDE + base] = q.y;
        Qt[(tx * 4 + 2) * QT_STRIDE + base] = q.z;
        Qt[(tx * 4 + 3) * QT_STRIDE + base] = q.w;
    }

    float rr[4];
#pragma unroll
    for (int ii = 0; ii < 4; ++ii) rr[ii] = RR[i0 + ty * 4 + ii];

    // out accumulators: 4 rows x 4 d-cols as packed d-pairs
    unsigned long long o2[4][2];
#pragma unroll
    for (int ii = 0; ii < 4; ++ii) { o2[ii][0] = 0ull; o2[ii][1] = 0ull; }
    float rsum = 0.0f;

    const float CF = 8.0f / 0.9f;  // sqrt(64)/(1-p); x8 exact -> rounding matches ref

    for (int jt = 0; jt < TILES_PER_CTA; ++jt) {
        const int j0 = jbase + jt * TN;
        __syncthreads();  // previous tile's GEMM2 done before refill

        // ---- fill Kt[k][swz(j,k)] (transposed + swizzled) ----
#pragma unroll
        for (int it = 0; it < 4; ++it) {
            int r = it * 32 + ty;                   // j row
            float4 kv = *(const float4*)(K + (size_t)(j0 + r) * DDIM + tx * 4);
            int base = 4 * ((r >> 2) ^ gsw) + (r & 3);
            Kt[(tx * 4 + 0) * KT_STRIDE + base] = kv.x;
            Kt[(tx * 4 + 1) * KT_STRIDE + base] = kv.y;
            Kt[(tx * 4 + 2) * KT_STRIDE + base] = kv.z;
            Kt[(tx * 4 + 3) * KT_STRIDE + base] = kv.w;
        }
        // ---- fill Vs[j][d] (direct copy) ----
#pragma unroll
        for (int it = 0; it < 4; ++it) {
            int v = it * NTHREADS + tid;
            int row = v >> 4, c4 = (v & 15) << 2;
            *(float4*)(Vs + row * 64 + c4) =
                *(const float4*)(V + (size_t)(j0 + row) * DDIM + c4);
        }

        // ---- prefetch U for this tile (hidden under GEMM1) ----
        float4 u[8];
#pragma unroll
        for (int ii = 0; ii < 4; ++ii) {
            const float* urow = U + (size_t)(i0 + ty * 4 + ii) * SDIM + j0;
            u[ii * 2]     = *(const float4*)(urow + tx * 4);
            u[ii * 2 + 1] = *(const float4*)(urow + 64 + tx * 4);
        }
        __syncthreads();

        // ---- GEMM1: S = Q @ K^T  (4x8 micro, f32x2 packed over j) ----
        unsigned long long s2[4][4];
#pragma unroll
        for (int ii = 0; ii < 4; ++ii)
#pragma unroll
            for (int jp = 0; jp < 4; ++jp) s2[ii][jp] = 0ull;

#pragma unroll 4
        for (int k = 0; k < 64; ++k) {
            const int gk = (k >> 2) & 7;
            float4 a = *(const float4*)(Qt + k * QT_STRIDE + 4 * (ty ^ gk));
            const float* krow = Kt + k * KT_STRIDE + 4 * (tx ^ gk);
            ulonglong2 b0 = *(const ulonglong2*)(krow);       // j pairs (0,1),(2,3)
            ulonglong2 b1 = *(const ulonglong2*)(krow + 64);  // +64 chunk
            unsigned long long a2[4];
            PACKDUP(a2[0], a.x); PACKDUP(a2[1], a.y);
            PACKDUP(a2[2], a.z); PACKDUP(a2[3], a.w);
#pragma unroll
            for (int ii = 0; ii < 4; ++ii) {
                FMA2(s2[ii][0], a2[ii], b0.x);
                FMA2(s2[ii][1], a2[ii], b0.y);
                FMA2(s2[ii][2], a2[ii], b1.x);
                FMA2(s2[ii][3], a2[ii], b1.y);
            }
        }

        // ---- elementwise: dropout, floor mask, accumulate R; stage t*r tile ----
        float tq[8][4];  // [e][ii] -> transposed store
#pragma unroll
        for (int ii = 0; ii < 4; ++ii) {
            float sv[8];
            UNPACK2(sv[0], sv[1], s2[ii][0]);
            UNPACK2(sv[2], sv[3], s2[ii][1]);
            UNPACK2(sv[4], sv[5], s2[ii][2]);
            UNPACK2(sv[6], sv[7], s2[ii][3]);
            const float uu[8] = {u[ii*2].x, u[ii*2].y, u[ii*2].z, u[ii*2].w,
                                 u[ii*2+1].x, u[ii*2+1].y, u[ii*2+1].z, u[ii*2+1].w};
            const float rrv = rr[ii];
#pragma unroll
            for (int e = 0; e < 8; ++e) {
                float t = (uu[e] >= 0.1f) ? sv[e] * CF : 0.0f;
                float rv = floorf(t * rrv);
                rsum += rv;
                tq[e][ii] = t * rv;
            }
        }
        // ---- write Ts[j][swz(i,j)]: one STS.128 per e (4 ii contiguous) ----
        {
            const int ibase = 4 * (ty ^ gsw);  // g(j)=(j>>2)&7 = tx&7 for all 8 e
#pragma unroll
            for (int e = 0; e < 8; ++e) {
                int jw = (e < 4) ? (tx * 4 + e) : (64 + tx * 4 + (e - 4));
                *(float4*)(Ts + jw * TST_STRIDE + ibase) =
                    make_float4(tq[e][0], tq[e][1], tq[e][2], tq[e][3]);
            }
        }
        __syncthreads();

        // ---- GEMM2: out_acc += T @ V  (a = broadcast LDS.128 over 4 ii) ----
#pragma unroll 4
        for (int jj = 0; jj < 128; ++jj) {
            const int gj = (jj >> 2) & 7;
            float4 av = *(const float4*)(Ts + jj * TST_STRIDE + 4 * (ty ^ gj));
            ulonglong2 bv = *(const ulonglong2*)(Vs + jj * 64 + tx * 4);
            unsigned long long a2[4];
            PACKDUP(a2[0], av.x); PACKDUP(a2[1], av.y);
            PACKDUP(a2[2], av.z); PACKDUP(a2[3], av.w);
#pragma unroll
            for (int ii = 0; ii < 4; ++ii) {
                FMA2(o2[ii][0], a2[ii], bv.x);
                FMA2(o2[ii][1], a2[ii], bv.y);
            }
        }
    }

    // ---- epilogue: write partial output (no atomics -> deterministic) ----
#pragma unroll
    for (int ii = 0; ii < 4; ++ii) {
        float x0, x1, x2, x3;
        UNPACK2(x0, x1, o2[ii][0]);
        UNPACK2(x2, x3, o2[ii][1]);
        const int gi = i0 + ty * 4 + ii;
        *(float4*)(&g_outpart[blockIdx.x][gi][tx * 4]) =
            make_float4(x0, x1, x2, x3);
    }

    // ---- deterministic block reduction of rsum ----
#pragma unroll
    for (int off = 16; off; off >>= 1)
        rsum += __shfl_xor_sync(0xffffffffu, rsum, off);
    float* red = sm;  // reuse Qt region (all warps past last GEMM2 barrier work)
    __syncthreads();
    if ((tid & 31) == 0) red[tid >> 5] = rsum;
    __syncthreads();
    if (tid == 0) {
        float tot = 0.0f;
        for (int w = 0; w < 16; ++w) tot += red[w];
        g_rpart[blockIdx.y * JSPLIT + blockIdx.x] = tot;
    }
}

// Reduce R deterministically (same tree in every block) and finalize output.
__global__ void __launch_bounds__(256) finalize_kernel(float* __restrict__ out)
{
    __shared__ float red[128];
    const int tid = threadIdx.x;
    if (tid < 128) red[tid] = g_rpart[tid];
    __syncthreads();
#pragma unroll
    for (int s = 64; s > 0; s >>= 1) {
        if (tid < s) red[tid] += red[tid + s];
        __syncthreads();
    }
    const float R = red[0];

    const int idx = blockIdx.x * 256 + tid;  // one float4 per thread
    const float* base = &g_outpart[0][0][0];
    const size_t part = (size_t)SDIM * DDIM;
    float4 a = *(const float4*)(base + (size_t)idx * 4);
    float4 b = *(const float4*)(base + part + (size_t)idx * 4);
    float4 c = *(const float4*)(base + 2 * part + (size_t)idx * 4);
    float4 d = *(const float4*)(base + 3 * part + (size_t)idx * 4);
    float4 o;
    o.x = (((a.x + b.x) + c.x) + d.x) / R;
    o.y = (((a.y + b.y) + c.y) + d.y) / R;
    o.z = (((a.z + b.z) + c.z) + d.z) / R;
    o.w = (((a.w + b.w) + c.w) + d.w) / R;
    *(float4*)(out + (size_t)idx * 4) = o;
}

extern "C" void kernel_launch(void* const* d_in, const int* in_sizes, int n_in,
                              void* d_out, int out_size)
{
    const float* Q  = (const float*)d_in[0];
    const float* K  = (const float*)d_in[1];
    const float* V  = (const float*)d_in[2];
    const float* U  = (const float*)d_in[3];
    const float* RR = (const float*)d_in[4];
    float* out = (float*)d_out;

    cudaFuncSetAttribute(fused_attn_main,
                         cudaFuncAttributeMaxDynamicSharedMemorySize, SMEM_BYTES);

    dim3 grid(JSPLIT, ROWB);
    fused_attn_main<<<grid, NTHREADS, SMEM_BYTES>>>(Q, K, V, U, RR);
    finalize_kernel<<<(SDIM * DDIM) / (4 * 256), 256>>>(out);
}

// round 4
// speedup vs baseline: 1.7728x; 1.7194x over previous
#include <cuda_runtime.h>
#include <cuda_bf16.h>
#include <cstdint>

#define SDIM 4096
#define DDIM 64
#define TM 128
#define TN 128
#define JSPLIT 4
#define ROWB (SDIM / TM)                     /* 32 */
#define TILES_PER_CTA (SDIM / (TN * JSPLIT)) /* 8 */
#define NCTA (ROWB * JSPLIT)                 /* 128 */
#define NTHREADS 256

// ---- smem: 8 bf16 tiles of [128][64], 128B rows, XOR-swizzled ----
#define SM_QA 0
#define SM_QB (SM_QA + 16384)
#define SM_QC (SM_QB + 16384)
#define SM_KA (SM_QC + 16384)
#define SM_KB (SM_KA + 16384)
#define SM_KC (SM_KB + 16384)
#define SM_VH (SM_KC + 16384)
#define SM_VL (SM_VH + 16384)
#define SM_RED SM_KA             /* reused post-loop for rsum partials */
#define SMEM_BYTES (SM_VL + 16384)

__device__ float g_outpart[JSPLIT][SDIM][DDIM];
__device__ float g_rpart[NCTA];

// ---------------- PTX helpers (all baseline sm_80/90 features) ----------------
__device__ __forceinline__ uint32_t smem_u32(const void* p) {
    uint32_t a;
    asm("{ .reg .u64 t; cvta.to.shared.u64 t, %1; cvt.u32.u64 %0, t; }"
        : "=r"(a) : "l"(p));
    return a;
}
#define LDSM4(d0, d1, d2, d3, a) \
    asm volatile("ldmatrix.sync.aligned.m8n8.x4.shared.b16 {%0,%1,%2,%3}, [%4];" \
                 : "=r"(d0), "=r"(d1), "=r"(d2), "=r"(d3) : "r"(a))
#define LDSM4T(d0, d1, d2, d3, a) \
    asm volatile("ldmatrix.sync.aligned.m8n8.x4.trans.shared.b16 {%0,%1,%2,%3}, [%4];" \
                 : "=r"(d0), "=r"(d1), "=r"(d2), "=r"(d3) : "r"(a))
#define MMA16816(c, a, b0_, b1_) \
    asm volatile("mma.sync.aligned.m16n8k16.row.col.f32.bf16.bf16.f32 " \
                 "{%0,%1,%2,%3}, {%4,%5,%6,%7}, {%8,%9}, {%0,%1,%2,%3};" \
                 : "+f"((c)[0]), "+f"((c)[1]), "+f"((c)[2]), "+f"((c)[3]) \
                 : "r"((a)[0]), "r"((a)[1]), "r"((a)[2]), "r"((a)[3]), \
                   "r"(b0_), "r"(b1_))
// packed bf16x2: low half = lo element
#define CVTPK(r, lo, hi) \
    asm("cvt.rn.satfinite.bf16x2.f32 %0, %1, %2;" : "=r"(r) : "f"(hi), "f"(lo))

__device__ __forceinline__ void split3_pair(float x, float y, uint32_t& h,
                                            uint32_t& m, uint32_t& l) {
    CVTPK(h, x, y);
    float rx = x - __uint_as_float(h << 16);
    float ry = y - __uint_as_float(h & 0xffff0000u);
    CVTPK(m, rx, ry);
    float sx = rx - __uint_as_float(m << 16);
    float sy = ry - __uint_as_float(m & 0xffff0000u);
    CVTPK(l, sx, sy);
}
__device__ __forceinline__ void split2_pair(float x, float y, uint32_t& h,
                                            uint32_t& l) {
    CVTPK(h, x, y);
    float rx = x - __uint_as_float(h << 16);
    float ry = y - __uint_as_float(h & 0xffff0000u);
    CVTPK(l, rx, ry);
}

// ------------------------------ main kernel ------------------------------
__global__ void __launch_bounds__(NTHREADS, 1) fused_attn_main(
    const float* __restrict__ Q, const float* __restrict__ K,
    const float* __restrict__ V, const float* __restrict__ U,
    const float* __restrict__ RR)
{
    extern __shared__ char smem[];
    const uint32_t sb = smem_u32(smem);
    const int tid = threadIdx.x;
    const int wid = tid >> 5;
    const int l = tid & 31;
    const int wr = wid >> 1;             // 0..3 : 32-row slice of i
    const int wc = wid & 1;              // 0..1 : 64-col slice of j (k-split)
    const int i0 = blockIdx.y * TM;
    const int jbase = blockIdx.x * (SDIM / JSPLIT);
    const float CF = 8.0f / 0.9f;

    // per-lane ldmatrix address components (128B rows, XOR swizzle key)
    const uint32_t keysw = (uint32_t)(l & 7) << 4;
    const uint32_t rowA = (uint32_t)(l & 15) * 128;            // Q / V patterns
    const uint32_t colA = (uint32_t)((l >> 4) << 4);
    const uint32_t rowB = (uint32_t)((l & 7) + 8 * (l >> 4)) * 128;  // K pattern
    const uint32_t colB = (uint32_t)(((l >> 3) & 1) << 4);

    // ---- Q -> 3-way bf16 split smem (once; tile-invariant) ----
#pragma unroll
    for (int p = 0; p < 8; ++p) {
        int c = tid + p * NTHREADS;          // float4 index, 0..2047
        int row = c >> 4, q4 = (c & 15) * 4;
        float4 x = *(const float4*)(Q + (size_t)(i0 + row) * DDIM + q4);
        uint32_t h01, m01, l01, h23, m23, l23;
        split3_pair(x.x, x.y, h01, m01, l01);
        split3_pair(x.z, x.w, h23, m23, l23);
        uint32_t b = (uint32_t)row * 128 + q4 * 2;
        uint32_t sw = b ^ ((b >> 3) & 0x70);
        *(uint2*)(smem + SM_QA + sw) = make_uint2(h01, h23);
        *(uint2*)(smem + SM_QB + sw) = make_uint2(m01, m23);
        *(uint2*)(smem + SM_QC + sw) = make_uint2(l01, l23);
    }

    // row_rand values for this warp's fragment rows
    float rr0[2], rr1[2];
#pragma unroll
    for (int mt = 0; mt < 2; ++mt) {
        rr0[mt] = RR[i0 + 32 * wr + 16 * mt + (l >> 2)];
        rr1[mt] = RR[i0 + 32 * wr + 16 * mt + 8 + (l >> 2)];
    }

    float oacc[2][8][4];
#pragma unroll
    for (int mt = 0; mt < 2; ++mt)
#pragma unroll
        for (int dt = 0; dt < 8; ++dt)
#pragma unroll
            for (int e = 0; e < 4; ++e) oacc[mt][dt][e] = 0.0f;
    float rsum = 0.0f;

#pragma unroll 1
    for (int jt = 0; jt < TILES_PER_CTA; ++jt) {
        const int j0 = jbase + jt * TN;

        // -- prefetch K/V tile into registers --
        float4 kreg[8], vreg[8];
#pragma unroll
        for (int p = 0; p < 8; ++p) {
            int c = tid + p * NTHREADS;
            int row = c >> 4, q4 = (c & 15) * 4;
            kreg[p] = *(const float4*)(K + (size_t)(j0 + row) * DDIM + q4);
            vreg[p] = *(const float4*)(V + (size_t)(j0 + row) * DDIM + q4);
        }
        __syncthreads();  // previous tile's ldmatrix reads complete

        // -- split-store K (3-way) and V (2-way) --
#pragma unroll
        for (int p = 0; p < 8; ++p) {
            int c = tid + p * NTHREADS;
            int row = c >> 4, q4 = (c & 15) * 4;
            uint32_t b = (uint32_t)row * 128 + q4 * 2;
            uint32_t sw = b ^ ((b >> 3) & 0x70);
            uint32_t h01, m01, l01, h23, m23, l23;
            split3_pair(kreg[p].x, kreg[p].y, h01, m01, l01);
            split3_pair(kreg[p].z, kreg[p].w, h23, m23, l23);
            *(uint2*)(smem + SM_KA + sw) = make_uint2(h01, h23);
            *(uint2*)(smem + SM_KB + sw) = make_uint2(m01, m23);
            *(uint2*)(smem + SM_KC + sw) = make_uint2(l01, l23);
            uint32_t vh01, vl01, vh23, vl23;
            split2_pair(vreg[p].x, vreg[p].y, vh01, vl01);
            split2_pair(vreg[p].z, vreg[p].w, vh23, vl23);
            *(uint2*)(smem + SM_VH + sw) = make_uint2(vh01, vh23);
            *(uint2*)(smem + SM_VL + sw) = make_uint2(vl01, vl23);
        }
        __syncthreads();

        // -- GEMM1: S = sum of 6 split products, warp patch 32x64 --
        float sacc[2][8][4];
#pragma unroll
        for (int mt = 0; mt < 2; ++mt)
#pragma unroll
            for (int nt = 0; nt < 8; ++nt)
#pragma unroll
                for (int e = 0; e < 4; ++e) sacc[mt][nt][e] = 0.0f;

#pragma unroll 1
        for (int p = 0; p < 6; ++p) {
            const int pa = (0x210100 >> (p * 4)) & 15;  // {0,0,1,0,1,2}
            const int pb = (0x012010 >> (p * 4)) & 15;  // {0,1,0,2,1,0}
            const uint32_t qb = sb + SM_QA + (uint32_t)pa * 16384;
            const uint32_t kb = sb + SM_KA + (uint32_t)pb * 16384;
#pragma unroll
            for (int kt = 0; kt < 4; ++kt) {
                uint32_t amat[2][4];
#pragma unroll
                for (int mt = 0; mt < 2; ++mt) {
                    uint32_t addr = qb + (uint32_t)(32 * wr + 16 * mt) * 128 +
                                    rowA + (((uint32_t)kt * 32 + colA) ^ keysw);
                    LDSM4(amat[mt][0], amat[mt][1], amat[mt][2], amat[mt][3], addr);
                }
                uint32_t bm[8][2];
#pragma unroll
                for (int u = 0; u < 4; ++u) {
                    uint32_t addr = kb + (uint32_t)(64 * wc + 16 * u) * 128 +
                                    rowB + (((uint32_t)kt * 32 + colB) ^ keysw);
                    LDSM4(bm[2 * u][0], bm[2 * u][1], bm[2 * u + 1][0],
                          bm[2 * u + 1][1], addr);
                }
#pragma unroll
                for (int mt = 0; mt < 2; ++mt)
#pragma unroll
                    for (int nt = 0; nt < 8; ++nt)
                        MMA16816(sacc[mt][nt], amat[mt], bm[nt][0], bm[nt][1]);
            }
        }

        // -- elementwise on fragments; build GEMM2 A-fragments in registers --
        uint32_t aH[2][4][4], aL[2][4][4];
#pragma unroll
        for (int mt = 0; mt < 2; ++mt) {
            const float* u0p = U + (size_t)(i0 + 32 * wr + 16 * mt + (l >> 2)) * SDIM +
                               j0 + 64 * wc + (l & 3) * 2;
            const float* u1p = u0p + 8 * SDIM;
            float2 u0v[8], u1v[8];
#pragma unroll
            for (int nt = 0; nt < 8; ++nt) {
                u0v[nt] = *(const float2*)(u0p + 8 * nt);
                u1v[nt] = *(const float2*)(u1p + 8 * nt);
            }
            const float ra = rr0[mt], rb = rr1[mt];
#pragma unroll
            for (int nt = 0; nt < 8; ++nt) {
                float t0 = (u0v[nt].x >= 0.1f) ? sacc[mt][nt][0] * CF : 0.0f;
                float t1 = (u0v[nt].y >= 0.1f) ? sacc[mt][nt][1] * CF : 0.0f;
                float t2 = (u1v[nt].x >= 0.1f) ? sacc[mt][nt][2] * CF : 0.0f;
                float t3 = (u1v[nt].y >= 0.1f) ? sacc[mt][nt][3] * CF : 0.0f;
                float r0 = floorf(t0 * ra), r1 = floorf(t1 * ra);
                float r2 = floorf(t2 * rb), r3 = floorf(t3 * rb);
                rsum += (r0 + r1) + (r2 + r3);
                float tr0 = t0 * r0, tr1 = t1 * r1, tr2 = t2 * r2, tr3 = t3 * r3;
                uint32_t h01, lo01, h23, lo23;
                split2_pair(tr0, tr1, h01, lo01);
                split2_pair(tr2, tr3, h23, lo23);
                const int kt2 = nt >> 1, sub = (nt & 1) * 2;
                aH[mt][kt2][sub] = h01; aH[mt][kt2][sub + 1] = h23;
                aL[mt][kt2][sub] = lo01; aL[mt][kt2][sub + 1] = lo23;
            }
        }

        // -- GEMM2: oacc += (TR_H + TR_L) x (V_H + V_L) [3 products], k-slice 64 --
#pragma unroll 1
        for (int p = 0; p < 3; ++p) {
            const int useL_A = (p == 2);
            const uint32_t vb = sb + ((p == 1) ? SM_VL : SM_VH);
#pragma unroll
            for (int kt = 0; kt < 4; ++kt) {
                uint32_t bm[8][2];
#pragma unroll
                for (int u = 0; u < 4; ++u) {
                    uint32_t addr = vb + (uint32_t)(64 * wc + 16 * kt) * 128 +
                                    rowA + (((uint32_t)u * 32 + colA) ^ keysw);
                    LDSM4T(bm[2 * u][0], bm[2 * u][1], bm[2 * u + 1][0],
                           bm[2 * u + 1][1], addr);
                }
#pragma unroll
                for (int mt = 0; mt < 2; ++mt) {
                    const uint32_t* afr = useL_A ? aL[mt][kt] : aH[mt][kt];
#pragma unroll
                    for (int dt = 0; dt < 8; ++dt)
                        MMA16816(oacc[mt][dt], afr, bm[dt][0], bm[dt][1]);
                }
            }
        }
    }

    // ---- cross-warp (wc) reduction of output partials via smem ----
    __syncthreads();
    float* rbuf = (float*)smem;  // 4 x 8KB at SM_QA
    if (wc == 1) {
#pragma unroll
        for (int mt = 0; mt < 2; ++mt)
#pragma unroll
            for (int dt = 0; dt < 8; ++dt)
#pragma unroll
                for (int e = 0; e < 4; ++e)
                    rbuf[wr * 2048 + ((mt * 8 + dt) * 4 + e) * 32 + l] =
                        oacc[mt][dt][e];
    }
    __syncthreads();
    if (wc == 0) {
#pragma unroll
        for (int mt = 0; mt < 2; ++mt)
#pragma unroll
            for (int dt = 0; dt < 8; ++dt) {
                float c0 = oacc[mt][dt][0] +
                           rbuf[wr * 2048 + ((mt * 8 + dt) * 4 + 0) * 32 + l];
                float c1 = oacc[mt][dt][1] +
                           rbuf[wr * 2048 + ((mt * 8 + dt) * 4 + 1) * 32 + l];
                float c2 = oacc[mt][dt][2] +
                           rbuf[wr * 2048 + ((mt * 8 + dt) * 4 + 2) * 32 + l];
                float c3 = oacc[mt][dt][3] +
                           rbuf[wr * 2048 + ((mt * 8 + dt) * 4 + 3) * 32 + l];
                int r0 = i0 + 32 * wr + 16 * mt + (l >> 2);
                int col = 8 * dt + (l & 3) * 2;
                *(float2*)(&g_outpart[blockIdx.x][r0][col]) = make_float2(c0, c1);
                *(float2*)(&g_outpart[blockIdx.x][r0 + 8][col]) = make_float2(c2, c3);
            }
    }

    // ---- deterministic rsum reduction ----
#pragma unroll
    for (int off = 16; off; off >>= 1)
        rsum += __shfl_xor_sync(0xffffffffu, rsum, off);
    float* red = (float*)(smem + SM_RED);
    __syncthreads();
    if (l == 0) red[wid] = rsum;
    __syncthreads();
    if (tid == 0) {
        float tot = 0.0f;
#pragma unroll
        for (int w = 0; w < 8; ++w) tot += red[w];
        g_rpart[blockIdx.y * JSPLIT + blockIdx.x] = tot;
    }
}

// Reduce R deterministically and finalize output.
__global__ void __launch_bounds__(256) finalize_kernel(float* __restrict__ out)
{
    __shared__ float red[128];
    const int tid = threadIdx.x;
    if (tid < 128) red[tid] = g_rpart[tid];
    __syncthreads();
#pragma unroll
    for (int s = 64; s > 0; s >>= 1) {
        if (tid < s) red[tid] += red[tid + s];
        __syncthreads();
    }
    const float R = red[0];

    const int idx = blockIdx.x * 256 + tid;
    const float* base = &g_outpart[0][0][0];
    const size_t part = (size_t)SDIM * DDIM;
    float4 a = *(const float4*)(base + (size_t)idx * 4);
    float4 b = *(const float4*)(base + part + (size_t)idx * 4);
    float4 c = *(const float4*)(base + 2 * part + (size_t)idx * 4);
    float4 d = *(const float4*)(base + 3 * part + (size_t)idx * 4);
    float4 o;
    o.x = (((a.x + b.x) + c.x) + d.x) / R;
    o.y = (((a.y + b.y) + c.y) + d.y) / R;
    o.z = (((a.z + b.z) + c.z) + d.z) / R;
    o.w = (((a.w + b.w) + c.w) + d.w) / R;
    *(float4*)(out + (size_t)idx * 4) = o;
}

extern "C" void kernel_launch(void* const* d_in, const int* in_sizes, int n_in,
                              void* d_out, int out_size)
{
    const float* Q  = (const float*)d_in[0];
    const float* K  = (const float*)d_in[1];
    const float* V  = (const float*)d_in[2];
    const float* U  = (const float*)d_in[3];
    const float* RR = (const float*)d_in[4];
    float* out = (float*)d_out;

    cudaFuncSetAttribute(fused_attn_main,
                         cudaFuncAttributeMaxDynamicSharedMemorySize, SMEM_BYTES);

    dim3 grid(JSPLIT, ROWB);
    fused_attn_main<<<grid, NTHREADS, SMEM_BYTES>>>(Q, K, V, U, RR);
    finalize_kernel<<<(SDIM * DDIM) / (4 * 256), 256>>>(out);
}

// round 5
// speedup vs baseline: 1.8925x; 1.0675x over previous
#include <cuda_runtime.h>
#include <cuda_bf16.h>
#include <cstdint>

#define SDIM 4096
#define DDIM 64
#define TM 128
#define TN 128
#define JSPLIT 4
#define ROWB (SDIM / TM)                     /* 32 */
#define TILES_PER_CTA (SDIM / (TN * JSPLIT)) /* 8 */
#define NCTA (ROWB * JSPLIT)                 /* 128 */
#define NTHREADS 256

// ---- smem: 8 bf16 tiles of [128][64], 128B rows, XOR-swizzled ----
#define SM_QA 0
#define SM_QB (SM_QA + 16384)
#define SM_QC (SM_QB + 16384)
#define SM_KA (SM_QC + 16384)
#define SM_KB (SM_KA + 16384)
#define SM_KC (SM_KB + 16384)
#define SM_VH (SM_KC + 16384)
#define SM_VL (SM_VH + 16384)
#define SM_RED SM_KA             /* reused post-loop for reductions */
#define SMEM_BYTES (SM_VL + 16384)

__device__ float g_outpart[JSPLIT][SDIM][DDIM];
__device__ float g_rpart[NCTA];
__device__ int g_arrive = 0;
__device__ int g_depart = 0;

// ---------------- PTX helpers (baseline sm_80/90 features only) ----------------
__device__ __forceinline__ uint32_t smem_u32(const void* p) {
    uint32_t a;
    asm("{ .reg .u64 t; cvta.to.shared.u64 t, %1; cvt.u32.u64 %0, t; }"
        : "=r"(a) : "l"(p));
    return a;
}
#define LDSM4(d0, d1, d2, d3, a) \
    asm volatile("ldmatrix.sync.aligned.m8n8.x4.shared.b16 {%0,%1,%2,%3}, [%4];" \
                 : "=r"(d0), "=r"(d1), "=r"(d2), "=r"(d3) : "r"(a))
#define LDSM4T(d0, d1, d2, d3, a) \
    asm volatile("ldmatrix.sync.aligned.m8n8.x4.trans.shared.b16 {%0,%1,%2,%3}, [%4];" \
                 : "=r"(d0), "=r"(d1), "=r"(d2), "=r"(d3) : "r"(a))
#define MMA16816(c, a, b0_, b1_) \
    asm volatile("mma.sync.aligned.m16n8k16.row.col.f32.bf16.bf16.f32 " \
                 "{%0,%1,%2,%3}, {%4,%5,%6,%7}, {%8,%9}, {%0,%1,%2,%3};" \
                 : "+f"((c)[0]), "+f"((c)[1]), "+f"((c)[2]), "+f"((c)[3]) \
                 : "r"((a)[0]), "r"((a)[1]), "r"((a)[2]), "r"((a)[3]), \
                   "r"(b0_), "r"(b1_))
#define CVTPK(r, lo, hi) \
    asm("cvt.rn.satfinite.bf16x2.f32 %0, %1, %2;" : "=r"(r) : "f"(hi), "f"(lo))

__device__ __forceinline__ void split3_pair(float x, float y, uint32_t& h,
                                            uint32_t& m, uint32_t& l) {
    CVTPK(h, x, y);
    float rx = x - __uint_as_float(h << 16);
    float ry = y - __uint_as_float(h & 0xffff0000u);
    CVTPK(m, rx, ry);
    float sx = rx - __uint_as_float(m << 16);
    float sy = ry - __uint_as_float(m & 0xffff0000u);
    CVTPK(l, sx, sy);
}
__device__ __forceinline__ void split2_pair(float x, float y, uint32_t& h,
                                            uint32_t& l) {
    CVTPK(h, x, y);
    float rx = x - __uint_as_float(h << 16);
    float ry = y - __uint_as_float(h & 0xffff0000u);
    CVTPK(l, rx, ry);
}

// ------------------------------ main kernel ------------------------------
__global__ void __launch_bounds__(NTHREADS, 1) fused_attn_main(
    const float* __restrict__ Q, const float* __restrict__ K,
    const float* __restrict__ V, const float* __restrict__ U,
    const float* __restrict__ RR, float* __restrict__ out)
{
    extern __shared__ char smem[];
    const uint32_t sb = smem_u32(smem);
    const int tid = threadIdx.x;
    const int wid = tid >> 5;
    const int l = tid & 31;
    const int wr = wid >> 1;             // 0..3 : 32-row slice of i
    const int wc = wid & 1;              // 0..1 : 64-col slice of j (k-split)
    const int i0 = blockIdx.y * TM;
    const int jbase = blockIdx.x * (SDIM / JSPLIT);
    const float CF = 8.0f / 0.9f;

    // per-lane ldmatrix address components (128B rows, XOR swizzle key)
    const uint32_t keysw = (uint32_t)(l & 7) << 4;
    const uint32_t rowA = (uint32_t)(l & 15) * 128;            // Q / V patterns
    const uint32_t colA = (uint32_t)((l >> 4) << 4);
    const uint32_t rowB = (uint32_t)((l & 7) + 8 * (l >> 4)) * 128;  // K pattern
    const uint32_t colB = (uint32_t)(((l >> 3) & 1) << 4);

    // ---- Q -> 3-way bf16 split smem (once; tile-invariant) ----
#pragma unroll
    for (int p = 0; p < 8; ++p) {
        int c = tid + p * NTHREADS;          // float4 index, 0..2047
        int row = c >> 4, q4 = (c & 15) * 4;
        float4 x = *(const float4*)(Q + (size_t)(i0 + row) * DDIM + q4);
        uint32_t h01, m01, l01, h23, m23, l23;
        split3_pair(x.x, x.y, h01, m01, l01);
        split3_pair(x.z, x.w, h23, m23, l23);
        uint32_t b = (uint32_t)row * 128 + q4 * 2;
        uint32_t sw = b ^ ((b >> 3) & 0x70);
        *(uint2*)(smem + SM_QA + sw) = make_uint2(h01, h23);
        *(uint2*)(smem + SM_QB + sw) = make_uint2(m01, m23);
        *(uint2*)(smem + SM_QC + sw) = make_uint2(l01, l23);
    }

    float rr0[2], rr1[2];
#pragma unroll
    for (int mt = 0; mt < 2; ++mt) {
        rr0[mt] = RR[i0 + 32 * wr + 16 * mt + (l >> 2)];
        rr1[mt] = RR[i0 + 32 * wr + 16 * mt + 8 + (l >> 2)];
    }

    float oacc[2][8][4];
#pragma unroll
    for (int mt = 0; mt < 2; ++mt)
#pragma unroll
        for (int dt = 0; dt < 8; ++dt)
#pragma unroll
            for (int e = 0; e < 4; ++e) oacc[mt][dt][e] = 0.0f;
    float rsum = 0.0f;

#pragma unroll 1
    for (int jt = 0; jt < TILES_PER_CTA; ++jt) {
        const int j0 = jbase + jt * TN;

        // -- prefetch K/V tile into registers --
        float4 kreg[8], vreg[8];
#pragma unroll
        for (int p = 0; p < 8; ++p) {
            int c = tid + p * NTHREADS;
            int row = c >> 4, q4 = (c & 15) * 4;
            kreg[p] = *(const float4*)(K + (size_t)(j0 + row) * DDIM + q4);
            vreg[p] = *(const float4*)(V + (size_t)(j0 + row) * DDIM + q4);
        }
        __syncthreads();  // previous tile's ldmatrix reads complete

        // -- split-store K (3-way) and V (2-way) --
#pragma unroll
        for (int p = 0; p < 8; ++p) {
            int c = tid + p * NTHREADS;
            int row = c >> 4, q4 = (c & 15) * 4;
            uint32_t b = (uint32_t)row * 128 + q4 * 2;
            uint32_t sw = b ^ ((b >> 3) & 0x70);
            uint32_t h01, m01, l01, h23, m23, l23;
            split3_pair(kreg[p].x, kreg[p].y, h01, m01, l01);
            split3_pair(kreg[p].z, kreg[p].w, h23, m23, l23);
            *(uint2*)(smem + SM_KA + sw) = make_uint2(h01, h23);
            *(uint2*)(smem + SM_KB + sw) = make_uint2(m01, m23);
            *(uint2*)(smem + SM_KC + sw) = make_uint2(l01, l23);
            uint32_t vh01, vl01, vh23, vl23;
            split2_pair(vreg[p].x, vreg[p].y, vh01, vl01);
            split2_pair(vreg[p].z, vreg[p].w, vh23, vl23);
            *(uint2*)(smem + SM_VH + sw) = make_uint2(vh01, vh23);
            *(uint2*)(smem + SM_VL + sw) = make_uint2(vl01, vl23);
        }
        __syncthreads();

        // -- GEMM1: S = 6 split products; A/B fragments hoisted per kt --
        float sacc[2][8][4];
#pragma unroll
        for (int mt = 0; mt < 2; ++mt)
#pragma unroll
            for (int nt = 0; nt < 8; ++nt)
#pragma unroll
                for (int e = 0; e < 4; ++e) sacc[mt][nt][e] = 0.0f;

#pragma unroll
        for (int kt = 0; kt < 4; ++kt) {
            uint32_t amat3[3][2][4];
#pragma unroll
            for (int pa = 0; pa < 3; ++pa)
#pragma unroll
                for (int mt = 0; mt < 2; ++mt) {
                    uint32_t addr = sb + SM_QA + (uint32_t)pa * 16384 +
                                    (uint32_t)(32 * wr + 16 * mt) * 128 +
                                    rowA + (((uint32_t)kt * 32 + colA) ^ keysw);
                    LDSM4(amat3[pa][mt][0], amat3[pa][mt][1], amat3[pa][mt][2],
                          amat3[pa][mt][3], addr);
                }
            // kept (pa,pb): pb=0 -> pa{0,1,2}; pb=1 -> pa{0,1}; pb=2 -> pa{0}
#pragma unroll
            for (int pb = 0; pb < 3; ++pb) {
                uint32_t bm[8][2];
#pragma unroll
                for (int u = 0; u < 4; ++u) {
                    uint32_t addr = sb + SM_KA + (uint32_t)pb * 16384 +
                                    (uint32_t)(64 * wc + 16 * u) * 128 +
                                    rowB + (((uint32_t)kt * 32 + colB) ^ keysw);
                    LDSM4(bm[2 * u][0], bm[2 * u][1], bm[2 * u + 1][0],
                          bm[2 * u + 1][1], addr);
                }
                const int npa = 3 - pb;
#pragma unroll
                for (int pa = 0; pa < 3; ++pa) {
                    if (pa >= npa) break;
#pragma unroll
                    for (int mt = 0; mt < 2; ++mt)
#pragma unroll
                        for (int nt = 0; nt < 8; ++nt)
                            MMA16816(sacc[mt][nt], amat3[pa][mt], bm[nt][0],
                                     bm[nt][1]);
                }
            }
        }

        // -- elementwise on fragments; build GEMM2 A-fragments in registers --
        uint32_t aH[2][4][4], aL[2][4][4];
#pragma unroll
        for (int mt = 0; mt < 2; ++mt) {
            const float* u0p = U + (size_t)(i0 + 32 * wr + 16 * mt + (l >> 2)) * SDIM +
                               j0 + 64 * wc + (l & 3) * 2;
            const float* u1p = u0p + 8 * SDIM;
            float2 u0v[8], u1v[8];
#pragma unroll
            for (int nt = 0; nt < 8; ++nt) {
                u0v[nt] = *(const float2*)(u0p + 8 * nt);
                u1v[nt] = *(const float2*)(u1p + 8 * nt);
            }
            const float ra = rr0[mt], rb = rr1[mt];
#pragma unroll
            for (int nt = 0; nt < 8; ++nt) {
                float t0 = (u0v[nt].x >= 0.1f) ? sacc[mt][nt][0] * CF : 0.0f;
                float t1 = (u0v[nt].y >= 0.1f) ? sacc[mt][nt][1] * CF : 0.0f;
                float t2 = (u1v[nt].x >= 0.1f) ? sacc[mt][nt][2] * CF : 0.0f;
                float t3 = (u1v[nt].y >= 0.1f) ? sacc[mt][nt][3] * CF : 0.0f;
                float r0 = floorf(t0 * ra), r1 = floorf(t1 * ra);
                float r2 = floorf(t2 * rb), r3 = floorf(t3 * rb);
                rsum += (r0 + r1) + (r2 + r3);
                float tr0 = t0 * r0, tr1 = t1 * r1, tr2 = t2 * r2, tr3 = t3 * r3;
                uint32_t h01, lo01, h23, lo23;
                split2_pair(tr0, tr1, h01, lo01);
                split2_pair(tr2, tr3, h23, lo23);
                const int kt2 = nt >> 1, sub = (nt & 1) * 2;
                aH[mt][kt2][sub] = h01; aH[mt][kt2][sub + 1] = h23;
                aL[mt][kt2][sub] = lo01; aL[mt][kt2][sub + 1] = lo23;
            }
        }

        // -- GEMM2: oacc += TRH*VH + TRL*VH + TRH*VL ; VH hoisted per kt --
#pragma unroll
        for (int kt = 0; kt < 4; ++kt) {
            uint32_t bmh[8][2];
#pragma unroll
            for (int u = 0; u < 4; ++u) {
                uint32_t addr = sb + SM_VH + (uint32_t)(64 * wc + 16 * kt) * 128 +
                                rowA + (((uint32_t)u * 32 + colA) ^ keysw);
                LDSM4T(bmh[2 * u][0], bmh[2 * u][1], bmh[2 * u + 1][0],
                       bmh[2 * u + 1][1], addr);
            }
#pragma unroll
            for (int mt = 0; mt < 2; ++mt)
#pragma unroll
                for (int dt = 0; dt < 8; ++dt)
                    MMA16816(oacc[mt][dt], aH[mt][kt], bmh[dt][0], bmh[dt][1]);
#pragma unroll
            for (int mt = 0; mt < 2; ++mt)
#pragma unroll
                for (int dt = 0; dt < 8; ++dt)
                    MMA16816(oacc[mt][dt], aL[mt][kt], bmh[dt][0], bmh[dt][1]);
            uint32_t bml[8][2];
#pragma unroll
            for (int u = 0; u < 4; ++u) {
                uint32_t addr = sb + SM_VL + (uint32_t)(64 * wc + 16 * kt) * 128 +
                                rowA + (((uint32_t)u * 32 + colA) ^ keysw);
                LDSM4T(bml[2 * u][0], bml[2 * u][1], bml[2 * u + 1][0],
                       bml[2 * u + 1][1], addr);
            }
#pragma unroll
            for (int mt = 0; mt < 2; ++mt)
#pragma unroll
                for (int dt = 0; dt < 8; ++dt)
                    MMA16816(oacc[mt][dt], aH[mt][kt], bml[dt][0], bml[dt][1]);
        }
    }

    // ---- cross-warp (wc) reduction of output partials via smem ----
    __syncthreads();
    float* rbuf = (float*)smem;  // 4 x 8KB at SM_QA
    if (wc == 1) {
#pragma unroll
        for (int mt = 0; mt < 2; ++mt)
#pragma unroll
            for (int dt = 0; dt < 8; ++dt)
#pragma unroll
                for (int e = 0; e < 4; ++e)
                    rbuf[wr * 2048 + ((mt * 8 + dt) * 4 + e) * 32 + l] =
                        oacc[mt][dt][e];
    }
    __syncthreads();
    if (wc == 0) {
#pragma unroll
        for (int mt = 0; mt < 2; ++mt)
#pragma unroll
            for (int dt = 0; dt < 8; ++dt) {
                float c0 = oacc[mt][dt][0] +
                           rbuf[wr * 2048 + ((mt * 8 + dt) * 4 + 0) * 32 + l];
                float c1 = oacc[mt][dt][1] +
                           rbuf[wr * 2048 + ((mt * 8 + dt) * 4 + 1) * 32 + l];
                float c2 = oacc[mt][dt][2] +
                           rbuf[wr * 2048 + ((mt * 8 + dt) * 4 + 2) * 32 + l];
                float c3 = oacc[mt][dt][3] +
                           rbuf[wr * 2048 + ((mt * 8 + dt) * 4 + 3) * 32 + l];
                int r0 = i0 + 32 * wr + 16 * mt + (l >> 2);
                int col = 8 * dt + (l & 3) * 2;
                *(float2*)(&g_outpart[blockIdx.x][r0][col]) = make_float2(c0, c1);
                *(float2*)(&g_outpart[blockIdx.x][r0 + 8][col]) = make_float2(c2, c3);
            }
    }

    // ---- deterministic rsum reduction ----
#pragma unroll
    for (int off = 16; off; off >>= 1)
        rsum += __shfl_xor_sync(0xffffffffu, rsum, off);
    float* red = (float*)(smem + SM_RED);
    __syncthreads();
    if (l == 0) red[wid] = rsum;
    __syncthreads();
    if (tid == 0) {
        float tot = 0.0f;
#pragma unroll
        for (int w = 0; w < 8; ++w) tot += red[w];
        g_rpart[blockIdx.y * JSPLIT + blockIdx.x] = tot;
    }

    // ---- device-wide barrier (all 128 CTAs co-resident: 128KB smem => 1/SM) ----
    __threadfence();
    __syncthreads();
    if (tid == 0) atomicAdd(&g_arrive, 1);

    if (blockIdx.x == 0) {
        if (tid == 0) {
            while (atomicAdd(&g_arrive, 0) < NCTA) __nanosleep(64);
            __threadfence();
        }
        __syncthreads();
        // redundant-per-CTA deterministic R reduction (fixed tree, same result)
        float* red2 = (float*)smem;
        if (tid < NCTA) red2[tid] = __ldcg(&g_rpart[tid]);
        __syncthreads();
#pragma unroll
        for (int s = 64; s > 0; s >>= 1) {
            if (tid < s) red2[tid] += red2[tid + s];
            __syncthreads();
        }
        const float R = red2[0];
        // finalize this CTA's 128 rows: sum 4 jsplit partials, divide, write
        const float* base = &g_outpart[0][0][0];
        const size_t part = (size_t)SDIM * DDIM;
        const size_t rowbase = (size_t)i0 * DDIM / 4;  // float4 units
#pragma unroll
        for (int p = 0; p < 8; ++p) {
            size_t idx = rowbase + (size_t)p * NTHREADS + tid;
            float4 a = __ldcg((const float4*)(base + idx * 4));
            float4 b = __ldcg((const float4*)(base + part + idx * 4));
            float4 c = __ldcg((const float4*)(base + 2 * part + idx * 4));
            float4 d = __ldcg((const float4*)(base + 3 * part + idx * 4));
            float4 o;
            o.x = (((a.x + b.x) + c.x) + d.x) / R;
            o.y = (((a.y + b.y) + c.y) + d.y) / R;
            o.z = (((a.z + b.z) + c.z) + d.z) / R;
            o.w = (((a.w + b.w) + c.w) + d.w) / R;
            *(float4*)(out + idx * 4) = o;
        }
    }

    // ---- depart + self-clean (counters return to 0 every call) ----
    __syncthreads();
    if (tid == 0) {
        int old = atomicAdd(&g_depart, 1);
        if (old == NCTA - 1) {
            atomicExch(&g_arrive, 0);
            atomicExch(&g_depart, 0);
            __threadfence();
        }
    }
}

extern "C" void kernel_launch(void* const* d_in, const int* in_sizes, int n_in,
                              void* d_out, int out_size)
{
    const float* Q  = (const float*)d_in[0];
    const float* K  = (const float*)d_in[1];
    const float* V  = (const float*)d_in[2];
    const float* U  = (const float*)d_in[3];
    const float* RR = (const float*)d_in[4];
    float* out = (float*)d_out;

    cudaFuncSetAttribute(fused_attn_main,
                         cudaFuncAttributeMaxDynamicSharedMemorySize, SMEM_BYTES);

    dim3 grid(JSPLIT, ROWB);
    fused_attn_main<<<grid, NTHREADS, SMEM_BYTES>>>(Q, K, V, U, RR, out);
}